// round 1
// baseline (speedup 1.0000x reference)
#include <cuda_runtime.h>
#include <math.h>

#define T_ 2048
#define B_ 2
#define E_ 1024
#define H_ 16
#define S_ 64
#define BH_ (B_*H_)

// Scratch (static device globals; allocation-free per harness rules)
__device__ float g_q [B_*H_*T_*S_];   // [b,h,t,d]  unscaled q
__device__ float g_k [B_*H_*T_*S_];   // [b,h,r,d]  k' = k/32 + Er[:,r]
__device__ float g_v [B_*H_*T_*S_];   // [b,h,r,d]
__device__ float g_yt[B_*E_*T_];      // [b, e, t]  == Z flat ([b,2048,1024] row-major)

// ---------------------------------------------------------------------------
// Kernel 1: QKV projections. q = xh @ Wq^T (per head), k' = (xh @ Wk^T)/32 + Er col, v.
// grid: (T/64, H, B), 256 threads, 4x4 register tile per thread.
// ---------------------------------------------------------------------------
__global__ __launch_bounds__(256) void qkv_kernel(
    const float* __restrict__ x,   // [T,B,E]
    const float* __restrict__ Wq,  // [H,S,S]
    const float* __restrict__ Wk,
    const float* __restrict__ Wv,
    const float* __restrict__ Er)  // [S,T]
{
    __shared__ float xs[64*65];
    __shared__ float ws[64*65];
    const int h  = blockIdx.y, b = blockIdx.z;
    const int t0 = blockIdx.x * 64;
    const int tid = threadIdx.x, ty = tid >> 4, tx = tid & 15;

    // load x tile: xs[tt][s] = x[t0+tt, b, h*64+s]
    for (int i = tid; i < 4096; i += 256) {
        int r = i >> 6, s = i & 63;
        xs[r*65 + s] = x[(size_t)(t0 + r) * (B_*E_) + b*E_ + h*S_ + s];
    }

    const float* W[3] = { Wq + h*4096, Wk + h*4096, Wv + h*4096 };
    const size_t base = (size_t)(b*H_ + h) * T_ + t0;

    for (int w = 0; w < 3; w++) {
        __syncthreads();
        for (int i = tid; i < 4096; i += 256)
            ws[(i >> 6)*65 + (i & 63)] = W[w][i];   // ws[d][s]
        __syncthreads();

        float acc[4][4] = {};
        #pragma unroll 8
        for (int s = 0; s < 64; s++) {
            float xr[4], wr[4];
            #pragma unroll
            for (int i = 0; i < 4; i++) xr[i] = xs[(ty*4+i)*65 + s];
            #pragma unroll
            for (int j = 0; j < 4; j++) wr[j] = ws[(tx*4+j)*65 + s];
            #pragma unroll
            for (int i = 0; i < 4; i++)
                #pragma unroll
                for (int j = 0; j < 4; j++)
                    acc[i][j] = fmaf(xr[i], wr[j], acc[i][j]);
        }

        if (w == 0) {
            #pragma unroll
            for (int i = 0; i < 4; i++)
                #pragma unroll
                for (int j = 0; j < 4; j++)
                    g_q[(base + ty*4+i)*S_ + tx*4+j] = acc[i][j];
        } else if (w == 1) {
            #pragma unroll
            for (int i = 0; i < 4; i++)
                #pragma unroll
                for (int j = 0; j < 4; j++) {
                    int t = t0 + ty*4 + i, d = tx*4 + j;
                    g_k[(base + ty*4+i)*S_ + d] =
                        acc[i][j]*(1.0f/32.0f) + Er[(size_t)d*T_ + t];
                }
        } else {
            #pragma unroll
            for (int i = 0; i < 4; i++)
                #pragma unroll
                for (int j = 0; j < 4; j++)
                    g_v[(base + ty*4+i)*S_ + tx*4+j] = acc[i][j];
        }
    }
}

// ---------------------------------------------------------------------------
// Kernel 2: causal flash attention per (b,h). BM=BN=64, D=64.
// scores = q . k'   (scaling + rel-bias already folded into k')
// Output written e-major into g_yt (== projection input Z, no permute kernel).
// grid: (T/64, B*H), 256 threads, dynamic smem 4*64*65*4 = 66560 B.
// ---------------------------------------------------------------------------
__global__ __launch_bounds__(256) void attn_kernel()
{
    extern __shared__ float sm[];
    float* Qs = sm;             // [64][65]
    float* Ks = sm + 64*65;     // [64][65]
    float* Vs = sm + 2*64*65;   // [64][65]
    float* Ps = sm + 3*64*65;   // [64][65]

    const int qi = blockIdx.x;
    const int bh = blockIdx.y;
    const int t0 = qi * 64;
    const int tid = threadIdx.x, ty = tid >> 4, tx = tid & 15;

    const float* qp = g_q + (size_t)bh * T_ * S_;
    const float* kp = g_k + (size_t)bh * T_ * S_;
    const float* vp = g_v + (size_t)bh * T_ * S_;

    for (int i = tid; i < 4096; i += 256) {
        int r = i >> 6, d = i & 63;
        Qs[r*65 + d] = qp[(size_t)(t0 + r)*S_ + d];
    }

    float m[4], l[4], o[4][4];
    #pragma unroll
    for (int i = 0; i < 4; i++) {
        m[i] = -INFINITY; l[i] = 0.0f;
        #pragma unroll
        for (int j = 0; j < 4; j++) o[i][j] = 0.0f;
    }

    for (int j = 0; j <= qi; j++) {
        __syncthreads();
        for (int i = tid; i < 4096; i += 256) {
            int r = i >> 6, d = i & 63;
            Ks[r*65 + d] = kp[(size_t)(j*64 + r)*S_ + d];
            Vs[r*65 + d] = vp[(size_t)(j*64 + r)*S_ + d];
        }
        __syncthreads();

        // S = Q @ K'^T   (4x4 per thread)
        float s[4][4] = {};
        #pragma unroll 8
        for (int d = 0; d < 64; d++) {
            float qv[4], kv[4];
            #pragma unroll
            for (int i = 0; i < 4; i++) qv[i] = Qs[(ty*4+i)*65 + d];
            #pragma unroll
            for (int c = 0; c < 4; c++) kv[c] = Ks[(tx*4+c)*65 + d];
            #pragma unroll
            for (int i = 0; i < 4; i++)
                #pragma unroll
                for (int c = 0; c < 4; c++)
                    s[i][c] = fmaf(qv[i], kv[c], s[i][c]);
        }

        // causal mask on the diagonal tile
        if (j == qi) {
            #pragma unroll
            for (int i = 0; i < 4; i++)
                #pragma unroll
                for (int c = 0; c < 4; c++)
                    if (tx*4 + c > ty*4 + i) s[i][c] = -1e30f;
        }

        // online softmax
        #pragma unroll
        for (int i = 0; i < 4; i++) {
            float v = fmaxf(fmaxf(s[i][0], s[i][1]), fmaxf(s[i][2], s[i][3]));
            #pragma unroll
            for (int off = 8; off >= 1; off >>= 1)
                v = fmaxf(v, __shfl_xor_sync(0xffffffffu, v, off));
            float mn = fmaxf(m[i], v);
            float alpha = __expf(m[i] - mn);
            m[i] = mn;

            float rs = 0.0f;
            #pragma unroll
            for (int c = 0; c < 4; c++) {
                s[i][c] = __expf(s[i][c] - mn);
                rs += s[i][c];
            }
            #pragma unroll
            for (int off = 8; off >= 1; off >>= 1)
                rs += __shfl_xor_sync(0xffffffffu, rs, off);
            l[i] = l[i]*alpha + rs;
            #pragma unroll
            for (int c = 0; c < 4; c++) o[i][c] *= alpha;
        }

        // stage P, then O += P @ V
        #pragma unroll
        for (int i = 0; i < 4; i++)
            #pragma unroll
            for (int c = 0; c < 4; c++)
                Ps[(ty*4+i)*65 + tx*4+c] = s[i][c];
        __syncthreads();

        #pragma unroll 8
        for (int r = 0; r < 64; r++) {
            float pv[4], vv[4];
            #pragma unroll
            for (int i = 0; i < 4; i++) pv[i] = Ps[(ty*4+i)*65 + r];
            #pragma unroll
            for (int c = 0; c < 4; c++) vv[c] = Vs[r*65 + tx*4+c];
            #pragma unroll
            for (int i = 0; i < 4; i++)
                #pragma unroll
                for (int c = 0; c < 4; c++)
                    o[i][c] = fmaf(pv[i], vv[c], o[i][c]);
        }
    }

    // normalize, stage through smem, write e-major (coalesced over t)
    __syncthreads();
    #pragma unroll
    for (int i = 0; i < 4; i++) {
        float inv = 1.0f / l[i];
        #pragma unroll
        for (int c = 0; c < 4; c++)
            Ps[(ty*4+i)*65 + tx*4+c] = o[i][c] * inv;
    }
    __syncthreads();

    const int b = bh >> 4, h = bh & 15;
    float* yt = g_yt + ((size_t)b*E_ + h*S_) * T_;
    for (int i = tid; i < 4096; i += 256) {
        int e = i >> 6, t = i & 63;
        yt[(size_t)e*T_ + t0 + t] = Ps[t*65 + e];
    }
}

// ---------------------------------------------------------------------------
// Kernel 3: output projection. out[m][o] = sum_j Z[m][j] * Wr[o][j] + br[o]
// Z = g_yt viewed as [4096][1024]. grid: (E/64, B*T/64), 256 threads.
// ---------------------------------------------------------------------------
__global__ __launch_bounds__(256) void proj_kernel(
    const float* __restrict__ Wr,  // [E,E]
    const float* __restrict__ br,  // [E]
    float* __restrict__ out)       // [B,T,E]
{
    __shared__ float As[64*33];
    __shared__ float Bs[32*65];
    const int o0 = blockIdx.x * 64;
    const int m0 = blockIdx.y * 64;
    const int tid = threadIdx.x, ty = tid >> 4, tx = tid & 15;

    float acc[4][4] = {};
    for (int k0 = 0; k0 < E_; k0 += 32) {
        __syncthreads();
        for (int i = tid; i < 2048; i += 256) {
            int r = i >> 5, kk = i & 31;
            As[r*33 + kk] = g_yt[(size_t)(m0 + r)*E_ + k0 + kk];
        }
        for (int i = tid; i < 2048; i += 256) {
            int oo = i >> 5, kk = i & 31;
            Bs[kk*65 + oo] = Wr[(size_t)(o0 + oo)*E_ + k0 + kk];
        }
        __syncthreads();

        #pragma unroll 8
        for (int kk = 0; kk < 32; kk++) {
            float a[4], bv[4];
            #pragma unroll
            for (int i = 0; i < 4; i++) a[i] = As[(ty*4+i)*33 + kk];
            #pragma unroll
            for (int c = 0; c < 4; c++) bv[c] = Bs[kk*65 + tx*4+c];
            #pragma unroll
            for (int i = 0; i < 4; i++)
                #pragma unroll
                for (int c = 0; c < 4; c++)
                    acc[i][c] = fmaf(a[i], bv[c], acc[i][c]);
        }
    }

    #pragma unroll
    for (int i = 0; i < 4; i++)
        #pragma unroll
        for (int c = 0; c < 4; c++)
            out[(size_t)(m0 + ty*4+i)*E_ + o0 + tx*4+c] = acc[i][c] + br[o0 + tx*4+c];
}

// ---------------------------------------------------------------------------
extern "C" void kernel_launch(void* const* d_in, const int* in_sizes, int n_in,
                              void* d_out, int out_size)
{
    const float* x  = (const float*)d_in[0];
    const float* Wq = (const float*)d_in[1];
    const float* Wk = (const float*)d_in[2];
    const float* Wv = (const float*)d_in[3];
    const float* Er = (const float*)d_in[4];
    const float* Wr = (const float*)d_in[5];
    const float* br = (const float*)d_in[6];
    float* out = (float*)d_out;

    qkv_kernel<<<dim3(T_/64, H_, B_), 256>>>(x, Wq, Wk, Wv, Er);

    const int smem_attn = 4 * 64 * 65 * (int)sizeof(float);  // 66560 B
    cudaFuncSetAttribute(attn_kernel,
                         cudaFuncAttributeMaxDynamicSharedMemorySize, smem_attn);
    attn_kernel<<<dim3(T_/64, BH_), 256, smem_attn>>>();

    proj_kernel<<<dim3(E_/64, (B_*T_)/64), 256>>>(Wr, br, out);
}

// round 4
// speedup vs baseline: 1.0989x; 1.0989x over previous
#include <cuda_runtime.h>
#include <math.h>

#define T_ 2048
#define B_ 2
#define E_ 1024
#define H_ 16
#define S_ 64
#define BH_ (B_*H_)

// Scratch (static device globals; allocation-free per harness rules)
__device__ float g_q [B_*H_*T_*S_];   // [b,h,t,d]  unscaled q
__device__ float g_k [B_*H_*T_*S_];   // [b,h,r,d]  k' = k/32 + Er[:,r]
__device__ float g_v [B_*H_*T_*S_];   // [b,h,r,d]
__device__ float g_yt[B_*E_*T_];      // [b, e, t]  == Z flat ([b,2048,1024] row-major)

// ---------------------------------------------------------------------------
// Kernel 1: QKV projections. q = xh @ Wq^T (per head), k' = (xh @ Wk^T)/32 + Er col, v.
// grid: (T/64, H, B), 256 threads, 4x4 register tile per thread.
// ---------------------------------------------------------------------------
__global__ __launch_bounds__(256) void qkv_kernel(
    const float* __restrict__ x,   // [T,B,E]
    const float* __restrict__ Wq,  // [H,S,S]
    const float* __restrict__ Wk,
    const float* __restrict__ Wv,
    const float* __restrict__ Er)  // [S,T]
{
    __shared__ float xs[64*65];
    __shared__ float ws[64*65];
    const int h  = blockIdx.y, b = blockIdx.z;
    const int t0 = blockIdx.x * 64;
    const int tid = threadIdx.x, ty = tid >> 4, tx = tid & 15;

    for (int i = tid; i < 4096; i += 256) {
        int r = i >> 6, s = i & 63;
        xs[r*65 + s] = x[(size_t)(t0 + r) * (B_*E_) + b*E_ + h*S_ + s];
    }

    const float* W[3] = { Wq + h*4096, Wk + h*4096, Wv + h*4096 };
    const size_t base = (size_t)(b*H_ + h) * T_ + t0;

    for (int w = 0; w < 3; w++) {
        __syncthreads();
        for (int i = tid; i < 4096; i += 256)
            ws[(i >> 6)*65 + (i & 63)] = W[w][i];   // ws[d][s]
        __syncthreads();

        float acc[4][4] = {};
        #pragma unroll 8
        for (int s = 0; s < 64; s++) {
            float xr[4], wr[4];
            #pragma unroll
            for (int i = 0; i < 4; i++) xr[i] = xs[(ty*4+i)*65 + s];
            #pragma unroll
            for (int j = 0; j < 4; j++) wr[j] = ws[(tx*4+j)*65 + s];
            #pragma unroll
            for (int i = 0; i < 4; i++)
                #pragma unroll
                for (int j = 0; j < 4; j++)
                    acc[i][j] = fmaf(xr[i], wr[j], acc[i][j]);
        }

        if (w == 0) {
            #pragma unroll
            for (int i = 0; i < 4; i++)
                #pragma unroll
                for (int j = 0; j < 4; j++)
                    g_q[(base + ty*4+i)*S_ + tx*4+j] = acc[i][j];
        } else if (w == 1) {
            #pragma unroll
            for (int i = 0; i < 4; i++)
                #pragma unroll
                for (int j = 0; j < 4; j++) {
                    int t = t0 + ty*4 + i, d = tx*4 + j;
                    g_k[(base + ty*4+i)*S_ + d] =
                        acc[i][j]*(1.0f/32.0f) + Er[(size_t)d*T_ + t];
                }
        } else {
            #pragma unroll
            for (int i = 0; i < 4; i++)
                #pragma unroll
                for (int j = 0; j < 4; j++)
                    g_v[(base + ty*4+i)*S_ + tx*4+j] = acc[i][j];
        }
    }
}

// ---------------------------------------------------------------------------
// Kernel 2: causal flash attention. BM=128, BN=64, D=64.
// 256 threads as 16(ty) x 16(tx); per-thread 8 rows x 4 cols.
// All smem operand reads are float4 (LDS.128), mostly broadcast.
// smem: Qs[64][132] (q^T: [d][t]), Ks[64][68] (k^T: [d][r]),
//       Vs[64][68] ([r][d]), Ps[64][132] (p^T: [r][i]).  Total 102400 B.
// ---------------------------------------------------------------------------
__global__ __launch_bounds__(256) void attn_kernel()
{
    extern __shared__ float sm[];
    float* Qs = sm;                  // [64][132]
    float* Ks = Qs + 64*132;         // [64][68]
    float* Vs = Ks + 64*68;          // [64][68]
    float* Ps = Vs + 64*68;          // [64][132]

    const int qi = (int)gridDim.x - 1 - (int)blockIdx.x;  // big tiles first
    const int bh = blockIdx.y;
    const int t0 = qi * 128;
    const int tid = threadIdx.x;
    const int ty = tid >> 4, tx = tid & 15;

    const float* qp = g_q + (size_t)bh * T_ * S_;
    const float* kp = g_k + (size_t)bh * T_ * S_;
    const float* vp = g_v + (size_t)bh * T_ * S_;

    // load Q tile transposed: Qs[d][r]
    {
        const int r  = tid >> 1;            // 0..127
        const int d0 = (tid & 1) * 32;
        #pragma unroll
        for (int qq = 0; qq < 8; qq++) {
            float4 v4 = *(const float4*)&qp[(size_t)(t0 + r) * S_ + d0 + qq*4];
            Qs[(d0 + qq*4 + 0)*132 + r] = v4.x;
            Qs[(d0 + qq*4 + 1)*132 + r] = v4.y;
            Qs[(d0 + qq*4 + 2)*132 + r] = v4.z;
            Qs[(d0 + qq*4 + 3)*132 + r] = v4.w;
        }
    }

    float m[8], l[8], o[8][4];
    #pragma unroll
    for (int i = 0; i < 8; i++) {
        m[i] = -INFINITY; l[i] = 0.0f;
        #pragma unroll
        for (int c = 0; c < 4; c++) o[i][c] = 0.0f;
    }

    const int jmax = 2*qi + 1;
    for (int j = 0; j <= jmax; j++) {
        __syncthreads();
        // load K transposed: Ks[d][r]; V natural: Vs[r][d]
        {
            const int r  = tid >> 2;          // 0..63
            const int d0 = (tid & 3) * 16;
            #pragma unroll
            for (int qq = 0; qq < 4; qq++) {
                float4 k4 = *(const float4*)&kp[(size_t)(j*64 + r) * S_ + d0 + qq*4];
                Ks[(d0 + qq*4 + 0)*68 + r] = k4.x;
                Ks[(d0 + qq*4 + 1)*68 + r] = k4.y;
                Ks[(d0 + qq*4 + 2)*68 + r] = k4.z;
                Ks[(d0 + qq*4 + 3)*68 + r] = k4.w;
            }
            #pragma unroll
            for (int qq = 0; qq < 4; qq++) {
                float4 v4 = *(const float4*)&vp[(size_t)(j*64 + r) * S_ + d0 + qq*4];
                *(float4*)&Vs[r*68 + d0 + qq*4] = v4;
            }
        }
        __syncthreads();

        // S = Q @ K'^T   (8x4 per thread)
        float s[8][4];
        #pragma unroll
        for (int i = 0; i < 8; i++)
            #pragma unroll
            for (int c = 0; c < 4; c++) s[i][c] = 0.0f;

        #pragma unroll 4
        for (int d = 0; d < 64; d++) {
            float4 qa = *(const float4*)&Qs[d*132 + ty*8];
            float4 qb = *(const float4*)&Qs[d*132 + ty*8 + 4];
            float4 k4 = *(const float4*)&Ks[d*68 + tx*4];
            float qv[8] = {qa.x, qa.y, qa.z, qa.w, qb.x, qb.y, qb.z, qb.w};
            float kv[4] = {k4.x, k4.y, k4.z, k4.w};
            #pragma unroll
            for (int i = 0; i < 8; i++)
                #pragma unroll
                for (int c = 0; c < 4; c++)
                    s[i][c] = fmaf(qv[i], kv[c], s[i][c]);
        }

        // causal mask (only the two straddling tiles)
        if (j >= 2*qi) {
            #pragma unroll
            for (int i = 0; i < 8; i++)
                #pragma unroll
                for (int c = 0; c < 4; c++)
                    if (j*64 + tx*4 + c > t0 + ty*8 + i) s[i][c] = -1e30f;
        }

        // online softmax (row reduction over the 16 tx lanes)
        #pragma unroll
        for (int i = 0; i < 8; i++) {
            float mx = fmaxf(fmaxf(s[i][0], s[i][1]), fmaxf(s[i][2], s[i][3]));
            #pragma unroll
            for (int off = 8; off >= 1; off >>= 1)
                mx = fmaxf(mx, __shfl_xor_sync(0xffffffffu, mx, off));
            float mn = fmaxf(m[i], mx);
            float alpha = __expf(m[i] - mn);
            m[i] = mn;
            float rs = 0.0f;
            #pragma unroll
            for (int c = 0; c < 4; c++) {
                s[i][c] = __expf(s[i][c] - mn);
                rs += s[i][c];
            }
            #pragma unroll
            for (int off = 8; off >= 1; off >>= 1)
                rs += __shfl_xor_sync(0xffffffffu, rs, off);
            l[i] = l[i]*alpha + rs;
            #pragma unroll
            for (int c = 0; c < 4; c++) o[i][c] *= alpha;
        }

        // stage P transposed: Ps[r][i]
        #pragma unroll
        for (int c = 0; c < 4; c++) {
            float4 p0 = make_float4(s[0][c], s[1][c], s[2][c], s[3][c]);
            float4 p1 = make_float4(s[4][c], s[5][c], s[6][c], s[7][c]);
            *(float4*)&Ps[(tx*4 + c)*132 + ty*8]     = p0;
            *(float4*)&Ps[(tx*4 + c)*132 + ty*8 + 4] = p1;
        }
        __syncthreads();

        // O += P @ V
        #pragma unroll 4
        for (int r = 0; r < 64; r++) {
            float4 pa = *(const float4*)&Ps[r*132 + ty*8];
            float4 pb = *(const float4*)&Ps[r*132 + ty*8 + 4];
            float4 v4 = *(const float4*)&Vs[r*68 + tx*4];
            float pv[8] = {pa.x, pa.y, pa.z, pa.w, pb.x, pb.y, pb.z, pb.w};
            float vv[4] = {v4.x, v4.y, v4.z, v4.w};
            #pragma unroll
            for (int i = 0; i < 8; i++)
                #pragma unroll
                for (int c = 0; c < 4; c++)
                    o[i][c] = fmaf(pv[i], vv[c], o[i][c]);
        }
    }

    // normalize and stage into Qs as [e][t] (Q no longer needed)
    __syncthreads();
    {
        float inv[8];
        #pragma unroll
        for (int i = 0; i < 8; i++) inv[i] = 1.0f / l[i];
        #pragma unroll
        for (int c = 0; c < 4; c++) {
            float4 y0 = make_float4(o[0][c]*inv[0], o[1][c]*inv[1],
                                    o[2][c]*inv[2], o[3][c]*inv[3]);
            float4 y1 = make_float4(o[4][c]*inv[4], o[5][c]*inv[5],
                                    o[6][c]*inv[6], o[7][c]*inv[7]);
            *(float4*)&Qs[(tx*4 + c)*132 + ty*8]     = y0;
            *(float4*)&Qs[(tx*4 + c)*132 + ty*8 + 4] = y1;
        }
    }
    __syncthreads();

    const int b = bh >> 4, h = bh & 15;
    float* yt = g_yt + ((size_t)b*E_ + h*S_) * T_;
    for (int idx = tid; idx < 64*128; idx += 256) {
        int e = idx >> 7, t = idx & 127;
        yt[(size_t)e*T_ + t0 + t] = Qs[e*132 + t];
    }
}

// ---------------------------------------------------------------------------
// Kernel 3: output projection. out[m][n] = sum_k Z[m][k] * Wr[n][k] + br[n]
// Z = g_yt viewed as [4096][1024]. 128x128 tiles, per-thread 8x8, KB=32.
// ---------------------------------------------------------------------------
#define KB_ 32
__global__ __launch_bounds__(256) void proj_kernel(
    const float* __restrict__ Wr,  // [E,E]
    const float* __restrict__ br,  // [E]
    float* __restrict__ out)       // [B,T,E]
{
    __shared__ float As[KB_*132];   // As[kk][m]
    __shared__ float Bs[KB_*132];   // Bs[kk][n]
    const int o0 = blockIdx.x * 128;
    const int m0 = blockIdx.y * 128;
    const int tid = threadIdx.x, ty = tid >> 4, tx = tid & 15;

    float acc[8][8];
    #pragma unroll
    for (int i = 0; i < 8; i++)
        #pragma unroll
        for (int c = 0; c < 8; c++) acc[i][c] = 0.0f;

    const int rr  = tid >> 1;          // 0..127
    const int kk0 = (tid & 1) * 16;

    for (int k0 = 0; k0 < E_; k0 += KB_) {
        __syncthreads();
        #pragma unroll
        for (int qq = 0; qq < 4; qq++) {
            float4 a4 = *(const float4*)&g_yt[(size_t)(m0 + rr)*E_ + k0 + kk0 + qq*4];
            As[(kk0 + qq*4 + 0)*132 + rr] = a4.x;
            As[(kk0 + qq*4 + 1)*132 + rr] = a4.y;
            As[(kk0 + qq*4 + 2)*132 + rr] = a4.z;
            As[(kk0 + qq*4 + 3)*132 + rr] = a4.w;
        }
        #pragma unroll
        for (int qq = 0; qq < 4; qq++) {
            float4 b4 = *(const float4*)&Wr[(size_t)(o0 + rr)*E_ + k0 + kk0 + qq*4];
            Bs[(kk0 + qq*4 + 0)*132 + rr] = b4.x;
            Bs[(kk0 + qq*4 + 1)*132 + rr] = b4.y;
            Bs[(kk0 + qq*4 + 2)*132 + rr] = b4.z;
            Bs[(kk0 + qq*4 + 3)*132 + rr] = b4.w;
        }
        __syncthreads();

        #pragma unroll 4
        for (int kk = 0; kk < KB_; kk++) {
            float4 a0 = *(const float4*)&As[kk*132 + ty*8];
            float4 a1 = *(const float4*)&As[kk*132 + ty*8 + 4];
            float4 b0 = *(const float4*)&Bs[kk*132 + tx*8];
            float4 b1 = *(const float4*)&Bs[kk*132 + tx*8 + 4];
            float av[8] = {a0.x, a0.y, a0.z, a0.w, a1.x, a1.y, a1.z, a1.w};
            float bv[8] = {b0.x, b0.y, b0.z, b0.w, b1.x, b1.y, b1.z, b1.w};
            #pragma unroll
            for (int i = 0; i < 8; i++)
                #pragma unroll
                for (int c = 0; c < 8; c++)
                    acc[i][c] = fmaf(av[i], bv[c], acc[i][c]);
        }
    }

    // bias in registers, then vectorized epilogue
    float4 bb0 = *(const float4*)&br[o0 + tx*8];
    float4 bb1 = *(const float4*)&br[o0 + tx*8 + 4];
    #pragma unroll
    for (int i = 0; i < 8; i++) {
        const size_t row = (size_t)(m0 + ty*8 + i) * E_ + o0 + tx*8;
        float4 r0 = make_float4(acc[i][0] + bb0.x, acc[i][1] + bb0.y,
                                acc[i][2] + bb0.z, acc[i][3] + bb0.w);
        float4 r1 = make_float4(acc[i][4] + bb1.x, acc[i][5] + bb1.y,
                                acc[i][6] + bb1.z, acc[i][7] + bb1.w);
        *(float4*)&out[row]     = r0;
        *(float4*)&out[row + 4] = r1;
    }
}

// ---------------------------------------------------------------------------
extern "C" void kernel_launch(void* const* d_in, const int* in_sizes, int n_in,
                              void* d_out, int out_size)
{
    const float* x  = (const float*)d_in[0];
    const float* Wq = (const float*)d_in[1];
    const float* Wk = (const float*)d_in[2];
    const float* Wv = (const float*)d_in[3];
    const float* Er = (const float*)d_in[4];
    const float* Wr = (const float*)d_in[5];
    const float* br = (const float*)d_in[6];
    float* out = (float*)d_out;

    qkv_kernel<<<dim3(T_/64, H_, B_), 256>>>(x, Wq, Wk, Wv, Er);

    const int smem_attn = (64*132 + 64*68 + 64*68 + 64*132) * (int)sizeof(float); // 102400
    cudaFuncSetAttribute(attn_kernel,
                         cudaFuncAttributeMaxDynamicSharedMemorySize, smem_attn);
    attn_kernel<<<dim3(T_/128, BH_), 256, smem_attn>>>();

    proj_kernel<<<dim3(E_/128, (B_*T_)/128), 256>>>(Wr, br, out);
}

// round 8
// speedup vs baseline: 1.3016x; 1.1845x over previous
#include <cuda_runtime.h>
#include <cuda_bf16.h>
#include <math.h>
#include <stdint.h>

#define T_ 2048
#define B_ 2
#define E_ 1024
#define H_ 16
#define S_ 64
#define BH_ (B_*H_)

// Scratch (static device globals; allocation-free per harness rules)
__device__ float g_q [B_*H_*T_*S_];          // [b,h,t,d]  unscaled q
__device__ float g_k [B_*H_*T_*S_];          // [b,h,r,d]  k' = k/32 + Er[:,r]
__device__ float g_v [B_*H_*T_*S_];          // [b,h,r,d]
__device__ __nv_bfloat16 g_zhi[B_*E_*T_];    // Z (proj input) hi, flat [4096][1024]
__device__ __nv_bfloat16 g_zlo[B_*E_*T_];    // Z lo
__device__ __nv_bfloat16 g_whi[E_*E_];       // Wr hi
__device__ __nv_bfloat16 g_wlo[E_*E_];       // Wr lo

// ===========================================================================
// mma.sync / ldmatrix / cp.async helpers (baseline sm_90/sm_100, NO tcgen05)
// ===========================================================================
__device__ __forceinline__ uint32_t smem_u32(const void* p) {
    uint32_t a;
    asm("{ .reg .u64 t; cvta.to.shared.u64 t, %1; cvt.u32.u64 %0, t; }"
        : "=r"(a) : "l"(p));
    return a;
}
__device__ __forceinline__ void ldsm4(uint32_t* r, uint32_t addr) {
    asm volatile("ldmatrix.sync.aligned.m8n8.x4.shared.b16 {%0,%1,%2,%3}, [%4];"
                 : "=r"(r[0]), "=r"(r[1]), "=r"(r[2]), "=r"(r[3]) : "r"(addr));
}
__device__ __forceinline__ void ldsm2(uint32_t* r, uint32_t addr) {
    asm volatile("ldmatrix.sync.aligned.m8n8.x2.shared.b16 {%0,%1}, [%2];"
                 : "=r"(r[0]), "=r"(r[1]) : "r"(addr));
}
__device__ __forceinline__ void mma_bf16(float* c, const uint32_t* a, const uint32_t* b) {
    asm volatile(
        "mma.sync.aligned.m16n8k16.row.col.f32.bf16.bf16.f32 "
        "{%0,%1,%2,%3}, {%4,%5,%6,%7}, {%8,%9}, {%0,%1,%2,%3};"
        : "+f"(c[0]), "+f"(c[1]), "+f"(c[2]), "+f"(c[3])
        : "r"(a[0]), "r"(a[1]), "r"(a[2]), "r"(a[3]), "r"(b[0]), "r"(b[1]));
}
__device__ __forceinline__ void cpa16(uint32_t dst, const void* src) {
    asm volatile("cp.async.cg.shared.global [%0], [%1], 16;" :: "r"(dst), "l"(src));
}

// ---------------------------------------------------------------------------
// Kernel 1: QKV projections, 8x4 register tiles, float4 LDS everywhere.
// grid: (T/128, H, B), 256 threads, dynamic smem 51200 B.
// ---------------------------------------------------------------------------
__global__ __launch_bounds__(256) void qkv_kernel(
    const float* __restrict__ x,   // [T,B,E]
    const float* __restrict__ Wq,  // [H,S,S]
    const float* __restrict__ Wk,
    const float* __restrict__ Wv,
    const float* __restrict__ Er)  // [S,T]
{
    extern __shared__ float qsm[];
    float* xsT = qsm;               // [64][132]  ([s][t])
    float* wsT = qsm + 64*132;      // [64][68]   ([s][d])
    const int h  = blockIdx.y, b = blockIdx.z;
    const int t0 = blockIdx.x * 128;
    const int tid = threadIdx.x, ty = tid >> 4, tx = tid & 15;

    {
        const int r  = tid >> 1;            // 0..127
        const int d0 = (tid & 1) * 32;
        #pragma unroll
        for (int q = 0; q < 8; q++) {
            float4 v4 = *(const float4*)&x[(size_t)(t0 + r)*(B_*E_) + b*E_ + h*S_ + d0 + q*4];
            xsT[(d0 + q*4 + 0)*132 + r] = v4.x;
            xsT[(d0 + q*4 + 1)*132 + r] = v4.y;
            xsT[(d0 + q*4 + 2)*132 + r] = v4.z;
            xsT[(d0 + q*4 + 3)*132 + r] = v4.w;
        }
    }

    const float* W[3] = { Wq + h*4096, Wk + h*4096, Wv + h*4096 };
    float* G[3] = { g_q, g_k, g_v };
    const size_t base = (size_t)(b*H_ + h) * T_ + t0;

    for (int w = 0; w < 3; w++) {
        __syncthreads();
        {
            const int d  = tid >> 2;          // 0..63
            const int s0 = (tid & 3) * 16;
            #pragma unroll
            for (int q = 0; q < 4; q++) {
                float4 w4 = *(const float4*)&W[w][d*64 + s0 + q*4];
                wsT[(s0 + q*4 + 0)*68 + d] = w4.x;
                wsT[(s0 + q*4 + 1)*68 + d] = w4.y;
                wsT[(s0 + q*4 + 2)*68 + d] = w4.z;
                wsT[(s0 + q*4 + 3)*68 + d] = w4.w;
            }
        }
        __syncthreads();

        float acc[8][4];
        #pragma unroll
        for (int i = 0; i < 8; i++)
            #pragma unroll
            for (int c = 0; c < 4; c++) acc[i][c] = 0.0f;

        #pragma unroll 4
        for (int s = 0; s < 64; s++) {
            float4 qa = *(const float4*)&xsT[s*132 + ty*8];
            float4 qb = *(const float4*)&xsT[s*132 + ty*8 + 4];
            float4 k4 = *(const float4*)&wsT[s*68 + tx*4];
            float xv[8] = {qa.x, qa.y, qa.z, qa.w, qb.x, qb.y, qb.z, qb.w};
            float wv[4] = {k4.x, k4.y, k4.z, k4.w};
            #pragma unroll
            for (int i = 0; i < 8; i++)
                #pragma unroll
                for (int c = 0; c < 4; c++)
                    acc[i][c] = fmaf(xv[i], wv[c], acc[i][c]);
        }

        if (w == 1) {
            #pragma unroll
            for (int i = 0; i < 8; i++) {
                int t = t0 + ty*8 + i;
                float4 o4;
                o4.x = acc[i][0]*(1.0f/32.0f) + Er[(size_t)(tx*4+0)*T_ + t];
                o4.y = acc[i][1]*(1.0f/32.0f) + Er[(size_t)(tx*4+1)*T_ + t];
                o4.z = acc[i][2]*(1.0f/32.0f) + Er[(size_t)(tx*4+2)*T_ + t];
                o4.w = acc[i][3]*(1.0f/32.0f) + Er[(size_t)(tx*4+3)*T_ + t];
                *(float4*)&G[1][(base + ty*8+i)*S_ + tx*4] = o4;
            }
        } else {
            #pragma unroll
            for (int i = 0; i < 8; i++) {
                float4 o4 = make_float4(acc[i][0], acc[i][1], acc[i][2], acc[i][3]);
                *(float4*)&G[w][(base + ty*8+i)*S_ + tx*4] = o4;
            }
        }
    }
}

// ---------------------------------------------------------------------------
// Kernel 2: causal flash attention. BM=128, BN=64, D=64.
// Epilogue writes bf16 hi/lo split of Z (flat layout == proj's [4096][1024]).
// ---------------------------------------------------------------------------
__global__ __launch_bounds__(256) void attn_kernel()
{
    extern __shared__ float sm[];
    float* Qs = sm;                  // [64][132]
    float* Ks = Qs + 64*132;         // [64][68]
    float* Vs = Ks + 64*68;          // [64][68]
    float* Ps = Vs + 64*68;          // [64][132]

    const int qi = (int)gridDim.x - 1 - (int)blockIdx.x;  // big tiles first
    const int bh = blockIdx.y;
    const int t0 = qi * 128;
    const int tid = threadIdx.x;
    const int ty = tid >> 4, tx = tid & 15;

    const float* qp = g_q + (size_t)bh * T_ * S_;
    const float* kp = g_k + (size_t)bh * T_ * S_;
    const float* vp = g_v + (size_t)bh * T_ * S_;

    {
        const int r  = tid >> 1;
        const int d0 = (tid & 1) * 32;
        #pragma unroll
        for (int qq = 0; qq < 8; qq++) {
            float4 v4 = *(const float4*)&qp[(size_t)(t0 + r) * S_ + d0 + qq*4];
            Qs[(d0 + qq*4 + 0)*132 + r] = v4.x;
            Qs[(d0 + qq*4 + 1)*132 + r] = v4.y;
            Qs[(d0 + qq*4 + 2)*132 + r] = v4.z;
            Qs[(d0 + qq*4 + 3)*132 + r] = v4.w;
        }
    }

    float m[8], l[8], o[8][4];
    #pragma unroll
    for (int i = 0; i < 8; i++) {
        m[i] = -INFINITY; l[i] = 0.0f;
        #pragma unroll
        for (int c = 0; c < 4; c++) o[i][c] = 0.0f;
    }

    const int jmax = 2*qi + 1;
    for (int j = 0; j <= jmax; j++) {
        __syncthreads();
        {
            const int r  = tid >> 2;
            const int d0 = (tid & 3) * 16;
            #pragma unroll
            for (int qq = 0; qq < 4; qq++) {
                float4 k4 = *(const float4*)&kp[(size_t)(j*64 + r) * S_ + d0 + qq*4];
                Ks[(d0 + qq*4 + 0)*68 + r] = k4.x;
                Ks[(d0 + qq*4 + 1)*68 + r] = k4.y;
                Ks[(d0 + qq*4 + 2)*68 + r] = k4.z;
                Ks[(d0 + qq*4 + 3)*68 + r] = k4.w;
            }
            #pragma unroll
            for (int qq = 0; qq < 4; qq++) {
                float4 v4 = *(const float4*)&vp[(size_t)(j*64 + r) * S_ + d0 + qq*4];
                *(float4*)&Vs[r*68 + d0 + qq*4] = v4;
            }
        }
        __syncthreads();

        float s[8][4];
        #pragma unroll
        for (int i = 0; i < 8; i++)
            #pragma unroll
            for (int c = 0; c < 4; c++) s[i][c] = 0.0f;

        #pragma unroll 4
        for (int d = 0; d < 64; d++) {
            float4 qa = *(const float4*)&Qs[d*132 + ty*8];
            float4 qb = *(const float4*)&Qs[d*132 + ty*8 + 4];
            float4 k4 = *(const float4*)&Ks[d*68 + tx*4];
            float qv[8] = {qa.x, qa.y, qa.z, qa.w, qb.x, qb.y, qb.z, qb.w};
            float kv[4] = {k4.x, k4.y, k4.z, k4.w};
            #pragma unroll
            for (int i = 0; i < 8; i++)
                #pragma unroll
                for (int c = 0; c < 4; c++)
                    s[i][c] = fmaf(qv[i], kv[c], s[i][c]);
        }

        if (j >= 2*qi) {
            #pragma unroll
            for (int i = 0; i < 8; i++)
                #pragma unroll
                for (int c = 0; c < 4; c++)
                    if (j*64 + tx*4 + c > t0 + ty*8 + i) s[i][c] = -1e30f;
        }

        #pragma unroll
        for (int i = 0; i < 8; i++) {
            float mx = fmaxf(fmaxf(s[i][0], s[i][1]), fmaxf(s[i][2], s[i][3]));
            #pragma unroll
            for (int off = 8; off >= 1; off >>= 1)
                mx = fmaxf(mx, __shfl_xor_sync(0xffffffffu, mx, off));
            float mn = fmaxf(m[i], mx);
            float alpha = __expf(m[i] - mn);
            m[i] = mn;
            float rs = 0.0f;
            #pragma unroll
            for (int c = 0; c < 4; c++) {
                s[i][c] = __expf(s[i][c] - mn);
                rs += s[i][c];
            }
            #pragma unroll
            for (int off = 8; off >= 1; off >>= 1)
                rs += __shfl_xor_sync(0xffffffffu, rs, off);
            l[i] = l[i]*alpha + rs;
            #pragma unroll
            for (int c = 0; c < 4; c++) o[i][c] *= alpha;
        }

        #pragma unroll
        for (int c = 0; c < 4; c++) {
            float4 p0 = make_float4(s[0][c], s[1][c], s[2][c], s[3][c]);
            float4 p1 = make_float4(s[4][c], s[5][c], s[6][c], s[7][c]);
            *(float4*)&Ps[(tx*4 + c)*132 + ty*8]     = p0;
            *(float4*)&Ps[(tx*4 + c)*132 + ty*8 + 4] = p1;
        }
        __syncthreads();

        #pragma unroll 4
        for (int r = 0; r < 64; r++) {
            float4 pa = *(const float4*)&Ps[r*132 + ty*8];
            float4 pb = *(const float4*)&Ps[r*132 + ty*8 + 4];
            float4 v4 = *(const float4*)&Vs[r*68 + tx*4];
            float pv[8] = {pa.x, pa.y, pa.z, pa.w, pb.x, pb.y, pb.z, pb.w};
            float vv[4] = {v4.x, v4.y, v4.z, v4.w};
            #pragma unroll
            for (int i = 0; i < 8; i++)
                #pragma unroll
                for (int c = 0; c < 4; c++)
                    o[i][c] = fmaf(pv[i], vv[c], o[i][c]);
        }
    }

    __syncthreads();
    {
        float inv[8];
        #pragma unroll
        for (int i = 0; i < 8; i++) inv[i] = 1.0f / l[i];
        #pragma unroll
        for (int c = 0; c < 4; c++) {
            float4 y0 = make_float4(o[0][c]*inv[0], o[1][c]*inv[1],
                                    o[2][c]*inv[2], o[3][c]*inv[3]);
            float4 y1 = make_float4(o[4][c]*inv[4], o[5][c]*inv[5],
                                    o[6][c]*inv[6], o[7][c]*inv[7]);
            *(float4*)&Qs[(tx*4 + c)*132 + ty*8]     = y0;
            *(float4*)&Qs[(tx*4 + c)*132 + ty*8 + 4] = y1;
        }
    }
    __syncthreads();

    // epilogue: bf16 hi/lo split of Z, e-major (flat layout == proj's [m][k])
    const int b = bh >> 4, h = bh & 15;
    const size_t basez = ((size_t)b*E_ + h*S_) * T_;
    for (int idx = tid; idx < 64*128; idx += 256) {
        int e = idx >> 7, t = idx & 127;
        float y = Qs[e*132 + t];
        __nv_bfloat16 hi = __float2bfloat16(y);
        size_t off = basez + (size_t)e*T_ + t0 + t;
        g_zhi[off] = hi;
        g_zlo[off] = __float2bfloat16(y - __bfloat162float(hi));
    }
}

// ---------------------------------------------------------------------------
// Kernel 3a: Wr -> bf16 hi/lo split
// ---------------------------------------------------------------------------
__global__ __launch_bounds__(256) void wconv_kernel(const float* __restrict__ Wr)
{
    size_t i = ((size_t)blockIdx.x*256 + threadIdx.x) * 4;
    float4 w = *(const float4*)&Wr[i];
    float v[4] = {w.x, w.y, w.z, w.w};
    #pragma unroll
    for (int q = 0; q < 4; q++) {
        __nv_bfloat16 hi = __float2bfloat16(v[q]);
        g_whi[i+q] = hi;
        g_wlo[i+q] = __float2bfloat16(v[q] - __bfloat162float(hi));
    }
}

// ---------------------------------------------------------------------------
// Kernel 3b: output projection via mma.sync (bf16, 3-term split).
// out[4096,1024] = Z @ Wr^T + br.
// 128x128 tile / CTA, BK=32, 8 warps (2x4), warp tile 64x32.
// cp.async double-buffered smem: 2 * 4 tiles * (128 rows * 80B) = 81920 B.
// ---------------------------------------------------------------------------
#define PTILE_ (128*80)     // bytes per operand tile (row stride 80B, 32 bf16 used)
#define PBUF_  (4*PTILE_)   // Ahi, Alo, Bhi, Blo
__global__ __launch_bounds__(256) void proj_mma_kernel(
    const float* __restrict__ br, float* __restrict__ out)
{
    extern __shared__ __align__(128) char ps[];
    const uint32_t sb = smem_u32(ps);
    const int tid = threadIdx.x, wid = tid >> 5, lane = tid & 31;
    const int n0 = blockIdx.x * 128, m0 = blockIdx.y * 128;
    const int wm = wid >> 2, wn = wid & 3;

    float acc[4][4][4];
    #pragma unroll
    for (int mf = 0; mf < 4; mf++)
        #pragma unroll
        for (int nf = 0; nf < 4; nf++)
            #pragma unroll
            for (int r = 0; r < 4; r++) acc[mf][nf][r] = 0.0f;

    // stage loader: 4 tiles, 512 x 16B each; 256 threads x 2 units per tile
    const int lrow = tid >> 2, lc16 = tid & 3;

    #define ISSUE(cc, bb) do {                                                  \
        const int k0i = (cc) * 32;                                              \
        uint32_t base = sb + (bb) * PBUF_;                                      \
        _Pragma("unroll")                                                       \
        for (int q = 0; q < 2; q++) {                                           \
            int row = lrow + q*64;                                              \
            uint32_t soff = (uint32_t)row*80 + (uint32_t)lc16*16;               \
            size_t ga = (size_t)(m0 + row)*E_ + k0i + lc16*8;                   \
            size_t gb = (size_t)(n0 + row)*E_ + k0i + lc16*8;                   \
            cpa16(base + 0*PTILE_ + soff, g_zhi + ga);                          \
            cpa16(base + 1*PTILE_ + soff, g_zlo + ga);                          \
            cpa16(base + 2*PTILE_ + soff, g_whi + gb);                          \
            cpa16(base + 3*PTILE_ + soff, g_wlo + gb);                          \
        }                                                                       \
        asm volatile("cp.async.commit_group;" ::: "memory");                    \
    } while (0)

    ISSUE(0, 0);
    for (int c = 0; c < 32; c++) {
        const int buf = c & 1;
        if (c + 1 < 32) {
            ISSUE(c + 1, buf ^ 1);
            asm volatile("cp.async.wait_group 1;" ::: "memory");
        } else {
            asm volatile("cp.async.wait_group 0;" ::: "memory");
        }
        __syncthreads();

        const uint32_t Ah = sb + buf*PBUF_;
        const uint32_t Al = Ah + PTILE_;
        const uint32_t Bh = Ah + 2*PTILE_;
        const uint32_t Bl = Ah + 3*PTILE_;

        #pragma unroll
        for (int ks = 0; ks < 2; ks++) {
            uint32_t ah[4][4], al[4][4], bh[4][2], bl[4][2];
            const uint32_t akoff = (uint32_t)(ks*32 + (lane >> 4)*16);
            const int am = lane & 15;
            #pragma unroll
            for (int mf = 0; mf < 4; mf++) {
                uint32_t ro = (uint32_t)(wm*64 + mf*16 + am)*80 + akoff;
                ldsm4(ah[mf], Ah + ro);
                ldsm4(al[mf], Al + ro);
            }
            const uint32_t bkoff = (uint32_t)(ks*32 + ((lane >> 3) & 1)*16);
            const int bn = lane & 7;
            #pragma unroll
            for (int nf = 0; nf < 4; nf++) {
                uint32_t ro = (uint32_t)(wn*32 + nf*8 + bn)*80 + bkoff;
                ldsm2(bh[nf], Bh + ro);
                ldsm2(bl[nf], Bl + ro);
            }
            #pragma unroll
            for (int mf = 0; mf < 4; mf++)
                #pragma unroll
                for (int nf = 0; nf < 4; nf++) {
                    mma_bf16(acc[mf][nf], ah[mf], bh[nf]);
                    mma_bf16(acc[mf][nf], ah[mf], bl[nf]);
                    mma_bf16(acc[mf][nf], al[mf], bh[nf]);
                }
        }
        __syncthreads();
    }

    // epilogue: direct stores + bias
    const int g = lane >> 2, tg = lane & 3;
    #pragma unroll
    for (int nf = 0; nf < 4; nf++) {
        const int col = n0 + wn*32 + nf*8 + tg*2;
        float2 bb = *(const float2*)&br[col];
        #pragma unroll
        for (int mf = 0; mf < 4; mf++) {
            const int row = m0 + wm*64 + mf*16 + g;
            float2 v0 = make_float2(acc[mf][nf][0] + bb.x, acc[mf][nf][1] + bb.y);
            float2 v1 = make_float2(acc[mf][nf][2] + bb.x, acc[mf][nf][3] + bb.y);
            *(float2*)&out[(size_t)row*E_ + col]       = v0;
            *(float2*)&out[(size_t)(row + 8)*E_ + col] = v1;
        }
    }
}

// ---------------------------------------------------------------------------
extern "C" void kernel_launch(void* const* d_in, const int* in_sizes, int n_in,
                              void* d_out, int out_size)
{
    const float* x  = (const float*)d_in[0];
    const float* Wq = (const float*)d_in[1];
    const float* Wk = (const float*)d_in[2];
    const float* Wv = (const float*)d_in[3];
    const float* Er = (const float*)d_in[4];
    const float* Wr = (const float*)d_in[5];
    const float* br = (const float*)d_in[6];
    float* out = (float*)d_out;

    const int smem_qkv = (64*132 + 64*68) * (int)sizeof(float);  // 51200
    cudaFuncSetAttribute(qkv_kernel,
                         cudaFuncAttributeMaxDynamicSharedMemorySize, smem_qkv);
    qkv_kernel<<<dim3(T_/128, H_, B_), 256, smem_qkv>>>(x, Wq, Wk, Wv, Er);

    wconv_kernel<<<(E_*E_)/(256*4), 256>>>(Wr);

    const int smem_attn = (64*132 + 64*68 + 64*68 + 64*132) * (int)sizeof(float); // 102400
    cudaFuncSetAttribute(attn_kernel,
                         cudaFuncAttributeMaxDynamicSharedMemorySize, smem_attn);
    attn_kernel<<<dim3(T_/128, BH_), 256, smem_attn>>>();

    const int smem_proj = 2 * PBUF_;  // 81920
    cudaFuncSetAttribute(proj_mma_kernel,
                         cudaFuncAttributeMaxDynamicSharedMemorySize, smem_proj);
    proj_mma_kernel<<<dim3(E_/128, (B_*T_)/128), 256, smem_proj>>>(br, out);
}

// round 9
// speedup vs baseline: 3.0165x; 2.3175x over previous
#include <cuda_runtime.h>
#include <cuda_bf16.h>
#include <math.h>
#include <stdint.h>

#define T_ 2048
#define B_ 2
#define E_ 1024
#define H_ 16
#define S_ 64
#define BH_ (B_*H_)
#define LOG2E_ 1.4426950408889634f

// Scratch (static device globals; allocation-free per harness rules)
__device__ __nv_bfloat16 g_qhi[B_*H_*T_*S_];   // [bh][t][d] q hi
__device__ __nv_bfloat16 g_qlo[B_*H_*T_*S_];
__device__ __nv_bfloat16 g_khi[B_*H_*T_*S_];   // [bh][r][d] k2 = (k/32 + Er)*log2e
__device__ __nv_bfloat16 g_klo[B_*H_*T_*S_];
__device__ __nv_bfloat16 g_vhi[B_*H_*T_*S_];   // [bh][r][d]
__device__ __nv_bfloat16 g_vlo[B_*H_*T_*S_];
__device__ __nv_bfloat16 g_zhi[B_*E_*T_];      // Z (proj input) hi, flat [4096][1024]
__device__ __nv_bfloat16 g_zlo[B_*E_*T_];
__device__ __nv_bfloat16 g_whi[E_*E_];         // Wr hi
__device__ __nv_bfloat16 g_wlo[E_*E_];

// ===========================================================================
// mma.sync / ldmatrix / cp.async helpers
// ===========================================================================
__device__ __forceinline__ uint32_t smem_u32(const void* p) {
    uint32_t a;
    asm("{ .reg .u64 t; cvta.to.shared.u64 t, %1; cvt.u32.u64 %0, t; }"
        : "=r"(a) : "l"(p));
    return a;
}
__device__ __forceinline__ void ldsm4(uint32_t* r, uint32_t addr) {
    asm volatile("ldmatrix.sync.aligned.m8n8.x4.shared.b16 {%0,%1,%2,%3}, [%4];"
                 : "=r"(r[0]), "=r"(r[1]), "=r"(r[2]), "=r"(r[3]) : "r"(addr));
}
__device__ __forceinline__ void ldsm4t(uint32_t* r, uint32_t addr) {
    asm volatile("ldmatrix.sync.aligned.m8n8.x4.trans.shared.b16 {%0,%1,%2,%3}, [%4];"
                 : "=r"(r[0]), "=r"(r[1]), "=r"(r[2]), "=r"(r[3]) : "r"(addr));
}
__device__ __forceinline__ void ldsm2(uint32_t* r, uint32_t addr) {
    asm volatile("ldmatrix.sync.aligned.m8n8.x2.shared.b16 {%0,%1}, [%2];"
                 : "=r"(r[0]), "=r"(r[1]) : "r"(addr));
}
__device__ __forceinline__ void mma_bf16(float* c, const uint32_t* a, const uint32_t* b) {
    asm volatile(
        "mma.sync.aligned.m16n8k16.row.col.f32.bf16.bf16.f32 "
        "{%0,%1,%2,%3}, {%4,%5,%6,%7}, {%8,%9}, {%0,%1,%2,%3};"
        : "+f"(c[0]), "+f"(c[1]), "+f"(c[2]), "+f"(c[3])
        : "r"(a[0]), "r"(a[1]), "r"(a[2]), "r"(a[3]), "r"(b[0]), "r"(b[1]));
}
__device__ __forceinline__ void cpa16(uint32_t dst, const void* src) {
    asm volatile("cp.async.cg.shared.global [%0], [%1], 16;" :: "r"(dst), "l"(src));
}
__device__ __forceinline__ float fexp2(float x) {
    float y; asm("ex2.approx.ftz.f32 %0, %1;" : "=f"(y) : "f"(x)); return y;
}
__device__ __forceinline__ uint32_t pack_bf2(float x, float y) {
    __nv_bfloat16 hx = __float2bfloat16(x), hy = __float2bfloat16(y);
    return (uint32_t)__bfloat16_as_ushort(hx) |
           ((uint32_t)__bfloat16_as_ushort(hy) << 16);
}
__device__ __forceinline__ void store4_split(__nv_bfloat16* hi, __nv_bfloat16* lo,
                                             float a, float b, float c, float d) {
    __nv_bfloat16 h0 = __float2bfloat16(a), h1 = __float2bfloat16(b);
    __nv_bfloat16 h2 = __float2bfloat16(c), h3 = __float2bfloat16(d);
    uint2 u;
    u.x = (uint32_t)__bfloat16_as_ushort(h0) | ((uint32_t)__bfloat16_as_ushort(h1) << 16);
    u.y = (uint32_t)__bfloat16_as_ushort(h2) | ((uint32_t)__bfloat16_as_ushort(h3) << 16);
    *(uint2*)hi = u;
    uint2 v;
    v.x = pack_bf2(a - __bfloat162float(h0), b - __bfloat162float(h1));
    v.y = pack_bf2(c - __bfloat162float(h2), d - __bfloat162float(h3));
    *(uint2*)lo = v;
}

// ---------------------------------------------------------------------------
// Kernel 1: QKV projections. Writes bf16 hi/lo of q, k2=(k/32+Er)*log2e, v.
// grid: (T/128, H, B), 256 threads, dynamic smem 51200 B.
// ---------------------------------------------------------------------------
__global__ __launch_bounds__(256) void qkv_kernel(
    const float* __restrict__ x,   // [T,B,E]
    const float* __restrict__ Wq,  // [H,S,S]
    const float* __restrict__ Wk,
    const float* __restrict__ Wv,
    const float* __restrict__ Er)  // [S,T]
{
    extern __shared__ float qsm[];
    float* xsT = qsm;               // [64][132]  ([s][t])
    float* wsT = qsm + 64*132;      // [64][68]   ([s][d])
    const int h  = blockIdx.y, b = blockIdx.z;
    const int t0 = blockIdx.x * 128;
    const int tid = threadIdx.x, ty = tid >> 4, tx = tid & 15;

    {
        const int r  = tid >> 1;
        const int d0 = (tid & 1) * 32;
        #pragma unroll
        for (int q = 0; q < 8; q++) {
            float4 v4 = *(const float4*)&x[(size_t)(t0 + r)*(B_*E_) + b*E_ + h*S_ + d0 + q*4];
            xsT[(d0 + q*4 + 0)*132 + r] = v4.x;
            xsT[(d0 + q*4 + 1)*132 + r] = v4.y;
            xsT[(d0 + q*4 + 2)*132 + r] = v4.z;
            xsT[(d0 + q*4 + 3)*132 + r] = v4.w;
        }
    }

    const float* W[3] = { Wq + h*4096, Wk + h*4096, Wv + h*4096 };
    const size_t base = (size_t)(b*H_ + h) * T_ + t0;

    for (int w = 0; w < 3; w++) {
        __syncthreads();
        {
            const int d  = tid >> 2;
            const int s0 = (tid & 3) * 16;
            #pragma unroll
            for (int q = 0; q < 4; q++) {
                float4 w4 = *(const float4*)&W[w][d*64 + s0 + q*4];
                wsT[(s0 + q*4 + 0)*68 + d] = w4.x;
                wsT[(s0 + q*4 + 1)*68 + d] = w4.y;
                wsT[(s0 + q*4 + 2)*68 + d] = w4.z;
                wsT[(s0 + q*4 + 3)*68 + d] = w4.w;
            }
        }
        __syncthreads();

        float acc[8][4];
        #pragma unroll
        for (int i = 0; i < 8; i++)
            #pragma unroll
            for (int c = 0; c < 4; c++) acc[i][c] = 0.0f;

        #pragma unroll 4
        for (int s = 0; s < 64; s++) {
            float4 qa = *(const float4*)&xsT[s*132 + ty*8];
            float4 qb = *(const float4*)&xsT[s*132 + ty*8 + 4];
            float4 k4 = *(const float4*)&wsT[s*68 + tx*4];
            float xv[8] = {qa.x, qa.y, qa.z, qa.w, qb.x, qb.y, qb.z, qb.w};
            float wv[4] = {k4.x, k4.y, k4.z, k4.w};
            #pragma unroll
            for (int i = 0; i < 8; i++)
                #pragma unroll
                for (int c = 0; c < 4; c++)
                    acc[i][c] = fmaf(xv[i], wv[c], acc[i][c]);
        }

        if (w == 0) {
            #pragma unroll
            for (int i = 0; i < 8; i++) {
                size_t idx = (base + ty*8+i)*S_ + tx*4;
                store4_split(g_qhi + idx, g_qlo + idx,
                             acc[i][0], acc[i][1], acc[i][2], acc[i][3]);
            }
        } else if (w == 1) {
            #pragma unroll
            for (int i = 0; i < 8; i++) {
                int t = t0 + ty*8 + i;
                float k0 = (acc[i][0]*(1.0f/32.0f) + Er[(size_t)(tx*4+0)*T_ + t]) * LOG2E_;
                float k1 = (acc[i][1]*(1.0f/32.0f) + Er[(size_t)(tx*4+1)*T_ + t]) * LOG2E_;
                float k2 = (acc[i][2]*(1.0f/32.0f) + Er[(size_t)(tx*4+2)*T_ + t]) * LOG2E_;
                float k3 = (acc[i][3]*(1.0f/32.0f) + Er[(size_t)(tx*4+3)*T_ + t]) * LOG2E_;
                size_t idx = (base + ty*8+i)*S_ + tx*4;
                store4_split(g_khi + idx, g_klo + idx, k0, k1, k2, k3);
            }
        } else {
            #pragma unroll
            for (int i = 0; i < 8; i++) {
                size_t idx = (base + ty*8+i)*S_ + tx*4;
                store4_split(g_vhi + idx, g_vlo + idx,
                             acc[i][0], acc[i][1], acc[i][2], acc[i][3]);
            }
        }
    }
}

// ---------------------------------------------------------------------------
// Kernel 2: flash attention on mma.sync. BM=128, BN=64, D=64, 8 warps.
// smem (bytes): Qh 0, Ql 18432, buffers at 36864 (2 x 36864):
//   within buf: Kh +0, Kl +9216, Vh +18432, Vl +27648. Total 110592 B.
// Row stride 144 B (72 bf16) -> 4-bank rotation, conflict-free ldmatrix.
// ---------------------------------------------------------------------------
__global__ __launch_bounds__(256) void attn_mma_kernel()
{
    extern __shared__ __align__(16) char asmem[];
    const uint32_t sb = smem_u32(asmem);
    const int tid = threadIdx.x, wid = tid >> 5, lane = tid & 31;
    const int qi = (int)gridDim.x - 1 - (int)blockIdx.x;   // big tiles first
    const int bh = blockIdx.y, t0 = qi * 128;

    const __nv_bfloat16* qh = g_qhi + (size_t)bh*T_*S_;
    const __nv_bfloat16* ql = g_qlo + (size_t)bh*T_*S_;
    const __nv_bfloat16* kh = g_khi + (size_t)bh*T_*S_;
    const __nv_bfloat16* kl = g_klo + (size_t)bh*T_*S_;
    const __nv_bfloat16* vh = g_vhi + (size_t)bh*T_*S_;
    const __nv_bfloat16* vl = g_vlo + (size_t)bh*T_*S_;

    // load Q (hi+lo), 128 rows x 8 chunks of 16B each
    #pragma unroll
    for (int it = 0; it < 4; it++) {
        int idx = it*256 + tid, row = idx >> 3, ch = idx & 7;
        uint32_t so = (uint32_t)row*144 + ch*16;
        size_t go = (size_t)(t0 + row)*64 + ch*8;
        cpa16(sb + so, qh + go);
        cpa16(sb + 18432 + so, ql + go);
    }
    asm volatile("cp.async.commit_group;" ::: "memory");

#define APREF(jj, bb) do {                                                      \
        uint32_t base_ = sb + 36864 + (bb)*36864;                               \
        _Pragma("unroll")                                                       \
        for (int it_ = 0; it_ < 2; it_++) {                                     \
            int idx_ = it_*256 + tid, row_ = idx_ >> 3, ch_ = idx_ & 7;         \
            uint32_t so_ = (uint32_t)row_*144 + ch_*16;                         \
            size_t go_ = (size_t)((jj)*64 + row_)*64 + ch_*8;                   \
            cpa16(base_ + so_,         kh + go_);                               \
            cpa16(base_ + 9216  + so_, kl + go_);                               \
            cpa16(base_ + 18432 + so_, vh + go_);                               \
            cpa16(base_ + 27648 + so_, vl + go_);                               \
        }                                                                       \
        asm volatile("cp.async.commit_group;" ::: "memory");                    \
    } while (0)

    APREF(0, 0);

    const uint32_t qoff = (uint32_t)(wid*16 + (lane & 15))*144 + ((lane >> 4) * 16);
    const uint32_t koff = (uint32_t)(lane & 7)*144 + (((lane >> 3) & 1) * 16);
    const uint32_t voff = (uint32_t)(((lane >> 3) & 1)*8 + (lane & 7))*144 + ((lane >> 4) * 16);

    float m0 = -1e30f, m1 = -1e30f, l0 = 0.0f, l1 = 0.0f;
    float o[8][4];
    #pragma unroll
    for (int nf = 0; nf < 8; nf++)
        #pragma unroll
        for (int r = 0; r < 4; r++) o[nf][r] = 0.0f;

    const int jmax = 2*qi + 1;
    for (int j = 0; j <= jmax; j++) {
        const int buf = j & 1;
        if (j < jmax) {
            APREF(j+1, buf^1);
            asm volatile("cp.async.wait_group 1;" ::: "memory");
        } else {
            asm volatile("cp.async.wait_group 0;" ::: "memory");
        }
        __syncthreads();

        const uint32_t kbb = sb + 36864 + buf*36864;
        const uint32_t vbb = kbb + 18432;

        // ---- S = Q @ K2^T (3-term bf16 split) ----
        float sc[8][4];
        #pragma unroll
        for (int nf = 0; nf < 8; nf++)
            #pragma unroll
            for (int r = 0; r < 4; r++) sc[nf][r] = 0.0f;

        #pragma unroll
        for (int ks = 0; ks < 4; ks++) {
            uint32_t aqh[4], aql[4];
            ldsm4(aqh, sb + qoff + ks*32);
            ldsm4(aql, sb + 18432 + qoff + ks*32);
            #pragma unroll
            for (int nf = 0; nf < 8; nf++) {
                uint32_t bh2[2], bl2[2];
                uint32_t ka = kbb + (uint32_t)nf*1152 + koff + ks*32;
                ldsm2(bh2, ka);
                ldsm2(bl2, ka + 9216);
                mma_bf16(sc[nf], aqh, bh2);
                mma_bf16(sc[nf], aqh, bl2);
                mma_bf16(sc[nf], aql, bh2);
            }
        }

        // ---- causal mask (diagonal-straddling tiles only) ----
        if (j >= 2*qi) {
            const int rb = t0 + wid*16 + (lane >> 2);
            const int cb = j*64 + (lane & 3)*2;
            #pragma unroll
            for (int nf = 0; nf < 8; nf++) {
                int c = cb + nf*8;
                if (c     > rb)     sc[nf][0] = -1e30f;
                if (c + 1 > rb)     sc[nf][1] = -1e30f;
                if (c     > rb + 8) sc[nf][2] = -1e30f;
                if (c + 1 > rb + 8) sc[nf][3] = -1e30f;
            }
        }

        // ---- online softmax (base-2; log2e folded into k2) ----
        float rm0 = -1e30f, rm1 = -1e30f;
        #pragma unroll
        for (int nf = 0; nf < 8; nf++) {
            rm0 = fmaxf(rm0, fmaxf(sc[nf][0], sc[nf][1]));
            rm1 = fmaxf(rm1, fmaxf(sc[nf][2], sc[nf][3]));
        }
        rm0 = fmaxf(rm0, __shfl_xor_sync(0xffffffffu, rm0, 1));
        rm0 = fmaxf(rm0, __shfl_xor_sync(0xffffffffu, rm0, 2));
        rm1 = fmaxf(rm1, __shfl_xor_sync(0xffffffffu, rm1, 1));
        rm1 = fmaxf(rm1, __shfl_xor_sync(0xffffffffu, rm1, 2));
        float mn0 = fmaxf(m0, rm0), mn1 = fmaxf(m1, rm1);
        float a0 = fexp2(m0 - mn0), a1 = fexp2(m1 - mn1);
        m0 = mn0; m1 = mn1;

        float rs0 = 0.0f, rs1 = 0.0f;
        #pragma unroll
        for (int nf = 0; nf < 8; nf++) {
            sc[nf][0] = fexp2(sc[nf][0] - mn0);
            sc[nf][1] = fexp2(sc[nf][1] - mn0);
            sc[nf][2] = fexp2(sc[nf][2] - mn1);
            sc[nf][3] = fexp2(sc[nf][3] - mn1);
            rs0 += sc[nf][0] + sc[nf][1];
            rs1 += sc[nf][2] + sc[nf][3];
        }
        rs0 += __shfl_xor_sync(0xffffffffu, rs0, 1);
        rs0 += __shfl_xor_sync(0xffffffffu, rs0, 2);
        rs1 += __shfl_xor_sync(0xffffffffu, rs1, 1);
        rs1 += __shfl_xor_sync(0xffffffffu, rs1, 2);
        l0 = l0*a0 + rs0;
        l1 = l1*a1 + rs1;
        #pragma unroll
        for (int nf = 0; nf < 8; nf++) {
            o[nf][0] *= a0; o[nf][1] *= a0;
            o[nf][2] *= a1; o[nf][3] *= a1;
        }

        // ---- pack P fragments (C frag pairs -> A frags), hi/lo split ----
        uint32_t ph[4][4], pl[4][4];
        #pragma unroll
        for (int kb = 0; kb < 4; kb++) {
            const float* s0 = sc[2*kb];
            const float* s1 = sc[2*kb+1];
            float rr[8] = {s0[0], s0[1], s0[2], s0[3], s1[0], s1[1], s1[2], s1[3]};
            #pragma unroll
            for (int q2 = 0; q2 < 4; q2++) {
                float xx = rr[q2*2], yy = rr[q2*2+1];
                __nv_bfloat16 hx = __float2bfloat16(xx), hy = __float2bfloat16(yy);
                ph[kb][q2] = (uint32_t)__bfloat16_as_ushort(hx) |
                             ((uint32_t)__bfloat16_as_ushort(hy) << 16);
                pl[kb][q2] = pack_bf2(xx - __bfloat162float(hx),
                                      yy - __bfloat162float(hy));
            }
        }

        // ---- O += P @ V (3-term bf16 split; V via ldmatrix.trans) ----
        #pragma unroll
        for (int kb = 0; kb < 4; kb++) {
            #pragma unroll
            for (int np = 0; np < 4; np++) {
                uint32_t v4h[4], v4l[4];
                uint32_t va = vbb + (uint32_t)kb*2304 + voff + np*32;
                ldsm4t(v4h, va);
                ldsm4t(v4l, va + 9216);
                mma_bf16(o[2*np],   ph[kb], v4h);
                mma_bf16(o[2*np],   ph[kb], v4l);
                mma_bf16(o[2*np],   pl[kb], v4h);
                mma_bf16(o[2*np+1], ph[kb], v4h + 2);
                mma_bf16(o[2*np+1], ph[kb], v4l + 2);
                mma_bf16(o[2*np+1], pl[kb], v4h + 2);
            }
        }
        __syncthreads();
    }

    // ---- epilogue: normalize, stage [d][t] in smem, write Z hi/lo e-major ----
    float* stage = (float*)(asmem + 36864);   // [64][132] floats
    {
        float inv0 = 1.0f / l0, inv1 = 1.0f / l1;
        const int g = lane >> 2, tg = lane & 3;
        const int tl = wid*16 + g;
        #pragma unroll
        for (int nf = 0; nf < 8; nf++) {
            int d = nf*8 + tg*2;
            stage[d*132 + tl]           = o[nf][0] * inv0;
            stage[(d+1)*132 + tl]       = o[nf][1] * inv0;
            stage[d*132 + tl + 8]       = o[nf][2] * inv1;
            stage[(d+1)*132 + tl + 8]   = o[nf][3] * inv1;
        }
    }
    __syncthreads();

    const int b = bh >> 4, h = bh & 15;
    const size_t basez = ((size_t)b*E_ + h*S_) * T_;
    #pragma unroll
    for (int it = 0; it < 32; it++) {
        int idx = it*256 + tid;
        int d = idx >> 7, t = idx & 127;
        float y = stage[d*132 + t];
        __nv_bfloat16 hi = __float2bfloat16(y);
        size_t off = basez + (size_t)d*T_ + t0 + t;
        g_zhi[off] = hi;
        g_zlo[off] = __float2bfloat16(y - __bfloat162float(hi));
    }
}

// ---------------------------------------------------------------------------
// Kernel 3a: Wr -> bf16 hi/lo split
// ---------------------------------------------------------------------------
__global__ __launch_bounds__(256) void wconv_kernel(const float* __restrict__ Wr)
{
    size_t i = ((size_t)blockIdx.x*256 + threadIdx.x) * 4;
    float4 w = *(const float4*)&Wr[i];
    float v[4] = {w.x, w.y, w.z, w.w};
    #pragma unroll
    for (int q = 0; q < 4; q++) {
        __nv_bfloat16 hi = __float2bfloat16(v[q]);
        g_whi[i+q] = hi;
        g_wlo[i+q] = __float2bfloat16(v[q] - __bfloat162float(hi));
    }
}

// ---------------------------------------------------------------------------
// Kernel 3b: output projection via mma.sync (bf16, 3-term split). Unchanged.
// ---------------------------------------------------------------------------
#define PTILE_ (128*80)
#define PBUF_  (4*PTILE_)
__global__ __launch_bounds__(256) void proj_mma_kernel(
    const float* __restrict__ br, float* __restrict__ out)
{
    extern __shared__ __align__(128) char ps[];
    const uint32_t sb = smem_u32(ps);
    const int tid = threadIdx.x, wid = tid >> 5, lane = tid & 31;
    const int n0 = blockIdx.x * 128, m0 = blockIdx.y * 128;
    const int wm = wid >> 2, wn = wid & 3;

    float acc[4][4][4];
    #pragma unroll
    for (int mf = 0; mf < 4; mf++)
        #pragma unroll
        for (int nf = 0; nf < 4; nf++)
            #pragma unroll
            for (int r = 0; r < 4; r++) acc[mf][nf][r] = 0.0f;

    const int lrow = tid >> 2, lc16 = tid & 3;

    #define ISSUE(cc, bb) do {                                                  \
        const int k0i = (cc) * 32;                                              \
        uint32_t base = sb + (bb) * PBUF_;                                      \
        _Pragma("unroll")                                                       \
        for (int q = 0; q < 2; q++) {                                           \
            int row = lrow + q*64;                                              \
            uint32_t soff = (uint32_t)row*80 + (uint32_t)lc16*16;               \
            size_t ga = (size_t)(m0 + row)*E_ + k0i + lc16*8;                   \
            size_t gb = (size_t)(n0 + row)*E_ + k0i + lc16*8;                   \
            cpa16(base + 0*PTILE_ + soff, g_zhi + ga);                          \
            cpa16(base + 1*PTILE_ + soff, g_zlo + ga);                          \
            cpa16(base + 2*PTILE_ + soff, g_whi + gb);                          \
            cpa16(base + 3*PTILE_ + soff, g_wlo + gb);                          \
        }                                                                       \
        asm volatile("cp.async.commit_group;" ::: "memory");                    \
    } while (0)

    ISSUE(0, 0);
    for (int c = 0; c < 32; c++) {
        const int buf = c & 1;
        if (c + 1 < 32) {
            ISSUE(c + 1, buf ^ 1);
            asm volatile("cp.async.wait_group 1;" ::: "memory");
        } else {
            asm volatile("cp.async.wait_group 0;" ::: "memory");
        }
        __syncthreads();

        const uint32_t Ah = sb + buf*PBUF_;
        const uint32_t Al = Ah + PTILE_;
        const uint32_t Bh = Ah + 2*PTILE_;
        const uint32_t Bl = Ah + 3*PTILE_;

        #pragma unroll
        for (int ks = 0; ks < 2; ks++) {
            uint32_t ah[4][4], al[4][4], bhf[4][2], blf[4][2];
            const uint32_t akoff = (uint32_t)(ks*32 + (lane >> 4)*16);
            const int am = lane & 15;
            #pragma unroll
            for (int mf = 0; mf < 4; mf++) {
                uint32_t ro = (uint32_t)(wm*64 + mf*16 + am)*80 + akoff;
                ldsm4(ah[mf], Ah + ro);
                ldsm4(al[mf], Al + ro);
            }
            const uint32_t bkoff = (uint32_t)(ks*32 + ((lane >> 3) & 1)*16);
            const int bn = lane & 7;
            #pragma unroll
            for (int nf = 0; nf < 4; nf++) {
                uint32_t ro = (uint32_t)(wn*32 + nf*8 + bn)*80 + bkoff;
                ldsm2(bhf[nf], Bh + ro);
                ldsm2(blf[nf], Bl + ro);
            }
            #pragma unroll
            for (int mf = 0; mf < 4; mf++)
                #pragma unroll
                for (int nf = 0; nf < 4; nf++) {
                    mma_bf16(acc[mf][nf], ah[mf], bhf[nf]);
                    mma_bf16(acc[mf][nf], ah[mf], blf[nf]);
                    mma_bf16(acc[mf][nf], al[mf], bhf[nf]);
                }
        }
        __syncthreads();
    }

    const int g = lane >> 2, tg = lane & 3;
    #pragma unroll
    for (int nf = 0; nf < 4; nf++) {
        const int col = n0 + wn*32 + nf*8 + tg*2;
        float2 bb = *(const float2*)&br[col];
        #pragma unroll
        for (int mf = 0; mf < 4; mf++) {
            const int row = m0 + wm*64 + mf*16 + g;
            float2 v0 = make_float2(acc[mf][nf][0] + bb.x, acc[mf][nf][1] + bb.y);
            float2 v1 = make_float2(acc[mf][nf][2] + bb.x, acc[mf][nf][3] + bb.y);
            *(float2*)&out[(size_t)row*E_ + col]       = v0;
            *(float2*)&out[(size_t)(row + 8)*E_ + col] = v1;
        }
    }
}

// ---------------------------------------------------------------------------
extern "C" void kernel_launch(void* const* d_in, const int* in_sizes, int n_in,
                              void* d_out, int out_size)
{
    const float* x  = (const float*)d_in[0];
    const float* Wq = (const float*)d_in[1];
    const float* Wk = (const float*)d_in[2];
    const float* Wv = (const float*)d_in[3];
    const float* Er = (const float*)d_in[4];
    const float* Wr = (const float*)d_in[5];
    const float* br = (const float*)d_in[6];
    float* out = (float*)d_out;

    const int smem_qkv = (64*132 + 64*68) * (int)sizeof(float);  // 51200
    cudaFuncSetAttribute(qkv_kernel,
                         cudaFuncAttributeMaxDynamicSharedMemorySize, smem_qkv);
    qkv_kernel<<<dim3(T_/128, H_, B_), 256, smem_qkv>>>(x, Wq, Wk, Wv, Er);

    wconv_kernel<<<(E_*E_)/(256*4), 256>>>(Wr);

    const int smem_attn = 110592;
    cudaFuncSetAttribute(attn_mma_kernel,
                         cudaFuncAttributeMaxDynamicSharedMemorySize, smem_attn);
    attn_mma_kernel<<<dim3(T_/128, BH_), 256, smem_attn>>>();

    const int smem_proj = 2 * PBUF_;  // 81920
    cudaFuncSetAttribute(proj_mma_kernel,
                         cudaFuncAttributeMaxDynamicSharedMemorySize, smem_proj);
    proj_mma_kernel<<<dim3(E_/128, (B_*T_)/128), 256, smem_proj>>>(br, out);
}